// round 3
// baseline (speedup 1.0000x reference)
#include <cuda_runtime.h>
#include <math.h>

// Problem dims (fixed by the dataset)
#define Bx 1024   // batch
#define TT 256    // warmup timesteps
#define II 64     // input signals
#define UU 1024   // LSTM units

// GEMM tile params
#define BM 64     // batch rows per block
#define BU 32     // units per block (each unit has 4 gates)
#define KT 32     // K tile

// Scratch state in device globals (no allocation allowed)
__device__ float g_h[2 * Bx * UU];   // double-buffered hidden state
__device__ float g_c[Bx * UU];      // cell state (element-owned, in-place)
__device__ float g_pred[Bx * II];   // dense-head prediction fed back as x

__device__ __forceinline__ float sigm(float z) { return 1.0f / (1.0f + expf(-z)); }

// One LSTM step, fused GEMM + gate update.
// z[b, g*U+u] = sum_i x[b,i]*Wk[i,g*U+u] + sum_k h[b,k]*Wr[k,g*U+u] + bias[g*U+u]
// Each thread: 8 batch rows x 1 unit x 4 gates = 32 accumulators.
__global__ __launch_bounds__(256, 4) void lstm_step_kernel(
    const float* __restrict__ x, int x_ld,
    const float* __restrict__ Wk, const float* __restrict__ Wr,
    const float* __restrict__ bias,
    const float* __restrict__ h_in, float* __restrict__ h_out,
    float* __restrict__ c)
{
    __shared__ float As[KT][BM + 1];     // +1 pad: conflict-free transposed store
    __shared__ float Ws[4][KT][BU];      // one tile per gate

    const int tid = threadIdx.x;
    const int tu  = tid & 31;            // unit within tile
    const int tb  = tid >> 5;            // batch group (0..7)
    const int u0  = blockIdx.x * BU;
    const int b0  = blockIdx.y * BM;

    float acc[4][8];
    #pragma unroll
    for (int g = 0; g < 4; g++)
        #pragma unroll
        for (int r = 0; r < 8; r++) acc[g][r] = 0.0f;

    #pragma unroll
    for (int phase = 0; phase < 2; phase++) {
        const float* A    = phase ? h_in : x;
        const int    lda  = phase ? UU   : x_ld;
        const float* W    = phase ? Wr   : Wk;
        const int    Klen = phase ? UU   : II;

        for (int k0 = 0; k0 < Klen; k0 += KT) {
            // Load A tile, transposed into SMEM. Consecutive tid -> consecutive k
            // (coalesced 128B global reads); padded stride kills store conflicts.
            #pragma unroll
            for (int i = 0; i < (BM * KT) / 256; i++) {
                int idx = tid + i * 256;
                int kk = idx & (KT - 1);
                int bb = idx >> 5;
                As[kk][bb] = A[(b0 + bb) * lda + (k0 + kk)];
            }
            // Load 4 gate weight tiles. Consecutive tid -> consecutive u (coalesced).
            #pragma unroll
            for (int i = 0; i < (4 * KT * BU) / 256; i++) {
                int idx = tid + i * 256;
                int uu = idx & (BU - 1);
                int kk = (idx >> 5) & (KT - 1);
                int g  = idx >> 10;
                Ws[g][kk][uu] = W[(k0 + kk) * (4 * UU) + g * UU + (u0 + uu)];
            }
            __syncthreads();

            #pragma unroll
            for (int kk = 0; kk < KT; kk++) {
                float w0 = Ws[0][kk][tu];   // conflict-free (consecutive tu)
                float w1 = Ws[1][kk][tu];
                float w2 = Ws[2][kk][tu];
                float w3 = Ws[3][kk][tu];
                #pragma unroll
                for (int r = 0; r < 8; r++) {
                    float a = As[kk][tb * 8 + r];   // warp-broadcast
                    acc[0][r] += a * w0;
                    acc[1][r] += a * w1;
                    acc[2][r] += a * w2;
                    acc[3][r] += a * w3;
                }
            }
            __syncthreads();
        }
    }

    // Epilogue: gate math + state update, all in registers.
    const int u = u0 + tu;
    const float bi = bias[u];
    const float bf = bias[UU + u];
    const float bg = bias[2 * UU + u];
    const float bo = bias[3 * UU + u];
    #pragma unroll
    for (int r = 0; r < 8; r++) {
        int gb = b0 + tb * 8 + r;
        float zi = acc[0][r] + bi;
        float zf = acc[1][r] + bf;
        float zg = acc[2][r] + bg;
        float zo = acc[3][r] + bo;
        float cv = c[gb * UU + u];
        float cn = sigm(zf) * cv + sigm(zi) * tanhf(zg);
        c[gb * UU + u] = cn;
        h_out[gb * UU + u] = sigm(zo) * tanhf(cn);   // coalesced: warp writes consecutive u
    }
}

// Dense head: pred[b,i] = sum_u h[b,u]*Wd[u,i] + bd[i]; also scatter selected
// columns into the output tensor for step s.
__global__ __launch_bounds__(64) void dense_kernel(
    const float* __restrict__ h, const float* __restrict__ Wd,
    const float* __restrict__ bd, const int* __restrict__ oidx, int n_idx,
    float* __restrict__ pred, float* __restrict__ out, int s, int S)
{
    __shared__ float hs[UU];
    __shared__ float ps[II];
    const int b = blockIdx.x;
    const int i = threadIdx.x;

    for (int k = i; k < UU; k += 64) hs[k] = h[b * UU + k];
    __syncthreads();

    float acc = bd[i];
    #pragma unroll 8
    for (int u = 0; u < UU; u++)
        acc += hs[u] * Wd[u * II + i];   // consecutive i -> coalesced, L2-resident

    pred[b * II + i] = acc;
    ps[i] = acc;
    __syncthreads();
    if (i < n_idx)
        out[(b * S + s) * n_idx + i] = ps[oidx[i]];
}

extern "C" void kernel_launch(void* const* d_in, const int* in_sizes, int n_in,
                              void* d_out, int out_size)
{
    const float* inputs = (const float*)d_in[0];   // [B, T, I]
    const float* Wk     = (const float*)d_in[1];   // [I, 4U]
    const float* Wr     = (const float*)d_in[2];   // [U, 4U]
    const float* bias   = (const float*)d_in[3];   // [4U]
    const float* Wd     = (const float*)d_in[4];   // [U, I]
    const float* bd     = (const float*)d_in[5];   // [I]
    const int*   oidx   = (const int*)d_in[6];     // output_indices
    float*       out    = (float*)d_out;

    const int n_idx = in_sizes[6];                 // 2
    const int S     = out_size / (Bx * n_idx);     // 64

    float *hb, *cb, *pb;
    cudaGetSymbolAddress((void**)&hb, g_h);
    cudaGetSymbolAddress((void**)&cb, g_c);
    cudaGetSymbolAddress((void**)&pb, g_pred);

    cudaMemsetAsync(hb, 0, sizeof(float) * 2 * Bx * UU);
    cudaMemsetAsync(cb, 0, sizeof(float) * Bx * UU);

    const dim3 grid(UU / BU, Bx / BM);   // (32, 16) = 512 blocks
    int cur = 0;

    // Warmup: 256 steps over the input sequence
    for (int t = 0; t < TT; t++) {
        lstm_step_kernel<<<grid, 256>>>(
            inputs + (size_t)t * II, TT * II,
            Wk, Wr, bias,
            hb + (size_t)cur * Bx * UU,
            hb + (size_t)(cur ^ 1) * Bx * UU,
            cb);
        cur ^= 1;
    }

    // First prediction
    dense_kernel<<<Bx, 64>>>(hb + (size_t)cur * Bx * UU, Wd, bd, oidx, n_idx,
                             pb, out, 0, S);

    // Autoregressive decode
    for (int s = 1; s < S; s++) {
        lstm_step_kernel<<<grid, 256>>>(
            pb, II,
            Wk, Wr, bias,
            hb + (size_t)cur * Bx * UU,
            hb + (size_t)(cur ^ 1) * Bx * UU,
            cb);
        cur ^= 1;
        dense_kernel<<<Bx, 64>>>(hb + (size_t)cur * Bx * UU, Wd, bd, oidx, n_idx,
                                 pb, out, s, S);
    }
}

// round 4
// speedup vs baseline: 1.1929x; 1.1929x over previous
#include <cuda_runtime.h>
#include <math.h>

// Problem dims (fixed by the dataset)
#define Bx 1024   // batch
#define TT 256    // warmup timesteps
#define II 64     // input signals
#define UU 1024   // LSTM units

// GEMM tile params
#define BM 128    // batch rows per block
#define BU 32     // units per block (x4 gates = 128 output cols)
#define KT 16     // K tile
#define NT 256    // threads per block
#define NTILES ((II + UU) / KT)   // 68 K-tiles per step (4 from Wk, 64 from Wr)

typedef unsigned long long ull;

// Scratch state in device globals (no allocation allowed)
__device__ float g_h[2 * Bx * UU];   // double-buffered hidden state
__device__ float g_c[Bx * UU];      // cell state (element-owned, in-place)
__device__ float g_pred[Bx * II];   // dense-head prediction fed back as x

__device__ __forceinline__ float sigm(float z) { return 1.0f / (1.0f + expf(-z)); }

__device__ __forceinline__ void cp_async16(void* dst, const void* src) {
    unsigned d = (unsigned)__cvta_generic_to_shared(dst);
    asm volatile("cp.async.ca.shared.global [%0], [%1], 16;\n" :: "r"(d), "l"(src) : "memory");
}
__device__ __forceinline__ void cp_commit() {
    asm volatile("cp.async.commit_group;\n" ::: "memory");
}
template<int N> __device__ __forceinline__ void cp_wait() {
    asm volatile("cp.async.wait_group %0;\n" :: "n"(N) : "memory");
}
// Duplicate one fp32 into both halves of a 64-bit packed operand
__device__ __forceinline__ ull pack2(float w) {
    ull r; unsigned u = __float_as_uint(w);
    asm("mov.b64 %0, {%1, %1};" : "=l"(r) : "r"(u));
    return r;
}
// Packed dual-fp32 FMA (sm_100): acc.{lo,hi} += a.{lo,hi} * w.{lo,hi}
__device__ __forceinline__ void ffma2(ull& acc, ull a, ull w) {
    asm("fma.rn.f32x2 %0, %1, %2, %0;" : "+l"(acc) : "l"(a), "l"(w));
}

// One LSTM step: z = x@Wk + h@Wr + b, gate math, state update — fused.
// Each thread: 16 batch rows (as 8 packed f32x2 pairs) x 1 unit x 4 gates.
__global__ __launch_bounds__(NT, 2) void lstm_step_kernel(
    const float* __restrict__ x, int x_ld,
    const float* __restrict__ Wk, const float* __restrict__ Wr,
    const float* __restrict__ bias,
    const float* __restrict__ h_in, float* __restrict__ h_out,
    float* __restrict__ c)
{
    __shared__ __align__(16) float As[2][KT][BM];        // A tile, k-major (transposed)
    __shared__ __align__(16) float Ws[2][4][KT][BU];     // weight tile per gate

    const int tid = threadIdx.x;
    const int tu  = tid & 31;            // unit within tile
    const int tb  = tid >> 5;            // batch group (0..7), 16 rows each
    const int u0  = blockIdx.x * BU;
    const int b0  = blockIdx.y * BM;

    ull acc[4][8];
    #pragma unroll
    for (int g = 0; g < 4; g++)
        #pragma unroll
        for (int p = 0; p < 8; p++) acc[g][p] = 0ull;

    // -------- tile load: Ws via cp.async (contiguous), As via LDG + transposed STS
    auto issue_tile = [&](int t, int buf) {
        const int tk = t * KT;
        const float* A;  int lda;  const float* W;  int koff;
        if (tk < II) { A = x;    lda = x_ld; W = Wk; koff = tk; }
        else         { A = h_in; lda = UU;   W = Wr; koff = tk - II; }

        // Weights: 4 gates x KT x BU floats = 512 16B chunks, 2 per thread
        #pragma unroll
        for (int i = 0; i < 2; i++) {
            int idx = tid + i * NT;
            int uu4 = idx & 7;
            int kk  = (idx >> 3) & (KT - 1);
            int g   = idx >> 7;
            cp_async16(&Ws[buf][g][kk][uu4 * 4],
                       W + (size_t)(koff + kk) * (4 * UU) + g * UU + u0 + uu4 * 4);
        }
        cp_commit();

        // A tile: KT x BM floats = 512 float4 chunks along k, 2 per thread,
        // stored transposed (k-major) so inner loop reads row-pairs contiguously.
        #pragma unroll
        for (int i = 0; i < 2; i++) {
            int idx = tid + i * NT;
            int bb  = idx & (BM - 1);
            int kq  = idx >> 7;          // 0..3 (4-float chunk along k)
            float4 v = *(const float4*)(A + (size_t)(b0 + bb) * lda + koff + kq * 4);
            As[buf][kq * 4 + 0][bb] = v.x;   // lanes have consecutive bb -> conflict-free
            As[buf][kq * 4 + 1][bb] = v.y;
            As[buf][kq * 4 + 2][bb] = v.z;
            As[buf][kq * 4 + 3][bb] = v.w;
        }
    };

    issue_tile(0, 0);

    for (int t = 0; t < NTILES; t++) {
        const int cur = t & 1;
        if (t + 1 < NTILES) { issue_tile(t + 1, cur ^ 1); cp_wait<1>(); }
        else                { cp_wait<0>(); }
        __syncthreads();

        #pragma unroll
        for (int kk = 0; kk < KT; kk++) {
            // 16 batch rows = 8 packed pairs, via 4 broadcast LDS.128
            const ulonglong2* ap = (const ulonglong2*)&As[cur][kk][tb * 16];
            ulonglong2 v0 = ap[0], v1 = ap[1], v2 = ap[2], v3 = ap[3];
            ull av[8] = { v0.x, v0.y, v1.x, v1.y, v2.x, v2.y, v3.x, v3.y };

            ull w0 = pack2(Ws[cur][0][kk][tu]);
            ull w1 = pack2(Ws[cur][1][kk][tu]);
            ull w2 = pack2(Ws[cur][2][kk][tu]);
            ull w3 = pack2(Ws[cur][3][kk][tu]);

            #pragma unroll
            for (int p = 0; p < 8; p++) {
                ffma2(acc[0][p], av[p], w0);
                ffma2(acc[1][p], av[p], w1);
                ffma2(acc[2][p], av[p], w2);
                ffma2(acc[3][p], av[p], w3);
            }
        }
        __syncthreads();   // all reads of 'cur' done before it is refilled at t+2
    }

    // -------- epilogue: gate math + state update, in registers
    const int u = u0 + tu;
    const float bi = bias[u];
    const float bf = bias[UU + u];
    const float bg = bias[2 * UU + u];
    const float bo = bias[3 * UU + u];

    #pragma unroll
    for (int p = 0; p < 8; p++) {
        #pragma unroll
        for (int half = 0; half < 2; half++) {
            const int row = b0 + tb * 16 + 2 * p + half;
            float zi = __uint_as_float((unsigned)(acc[0][p] >> (half * 32))) + bi;
            float zf = __uint_as_float((unsigned)(acc[1][p] >> (half * 32))) + bf;
            float zg = __uint_as_float((unsigned)(acc[2][p] >> (half * 32))) + bg;
            float zo = __uint_as_float((unsigned)(acc[3][p] >> (half * 32))) + bo;
            float cv = c[(size_t)row * UU + u];
            float cn = sigm(zf) * cv + sigm(zi) * tanhf(zg);
            c[(size_t)row * UU + u] = cn;
            h_out[(size_t)row * UU + u] = sigm(zo) * tanhf(cn);  // coalesced in u
        }
    }
}

// Dense head: pred[b,i] = sum_u h[b,u]*Wd[u,i] + bd[i]; scatter selected
// columns into the output tensor for step s.
__global__ __launch_bounds__(64) void dense_kernel(
    const float* __restrict__ h, const float* __restrict__ Wd,
    const float* __restrict__ bd, const int* __restrict__ oidx, int n_idx,
    float* __restrict__ pred, float* __restrict__ out, int s, int S)
{
    __shared__ float hs[UU];
    __shared__ float ps[II];
    const int b = blockIdx.x;
    const int i = threadIdx.x;

    for (int k = i; k < UU; k += 64) hs[k] = h[b * UU + k];
    __syncthreads();

    float acc = bd[i];
    #pragma unroll 8
    for (int u = 0; u < UU; u++)
        acc += hs[u] * Wd[u * II + i];

    pred[b * II + i] = acc;
    ps[i] = acc;
    __syncthreads();
    if (i < n_idx)
        out[(b * S + s) * n_idx + i] = ps[oidx[i]];
}

extern "C" void kernel_launch(void* const* d_in, const int* in_sizes, int n_in,
                              void* d_out, int out_size)
{
    const float* inputs = (const float*)d_in[0];   // [B, T, I]
    const float* Wk     = (const float*)d_in[1];   // [I, 4U]
    const float* Wr     = (const float*)d_in[2];   // [U, 4U]
    const float* bias   = (const float*)d_in[3];   // [4U]
    const float* Wd     = (const float*)d_in[4];   // [U, I]
    const float* bd     = (const float*)d_in[5];   // [I]
    const int*   oidx   = (const int*)d_in[6];     // output_indices
    float*       out    = (float*)d_out;

    const int n_idx = in_sizes[6];                 // 2
    const int S     = out_size / (Bx * n_idx);     // 64

    float *hb, *cb, *pb;
    cudaGetSymbolAddress((void**)&hb, g_h);
    cudaGetSymbolAddress((void**)&cb, g_c);
    cudaGetSymbolAddress((void**)&pb, g_pred);

    cudaMemsetAsync(hb, 0, sizeof(float) * 2 * Bx * UU);
    cudaMemsetAsync(cb, 0, sizeof(float) * Bx * UU);

    const dim3 grid(UU / BU, Bx / BM);   // (32, 8) = 256 blocks -> single wave @ 2/SM
    int cur = 0;

    // Warmup: 256 steps over the input sequence
    for (int t = 0; t < TT; t++) {
        lstm_step_kernel<<<grid, NT>>>(
            inputs + (size_t)t * II, TT * II,
            Wk, Wr, bias,
            hb + (size_t)cur * Bx * UU,
            hb + (size_t)(cur ^ 1) * Bx * UU,
            cb);
        cur ^= 1;
    }

    // First prediction
    dense_kernel<<<Bx, 64>>>(hb + (size_t)cur * Bx * UU, Wd, bd, oidx, n_idx,
                             pb, out, 0, S);

    // Autoregressive decode
    for (int s = 1; s < S; s++) {
        lstm_step_kernel<<<grid, NT>>>(
            pb, II,
            Wk, Wr, bias,
            hb + (size_t)cur * Bx * UU,
            hb + (size_t)(cur ^ 1) * Bx * UU,
            cb);
        cur ^= 1;
        dense_kernel<<<Bx, 64>>>(hb + (size_t)cur * Bx * UU, Wd, bd, oidx, n_idx,
                                 pb, out, s, S);
    }
}

// round 6
// speedup vs baseline: 3.4871x; 2.9231x over previous
#include <cuda_runtime.h>
#include <cuda_bf16.h>
#include <cstdint>
#include <math.h>

// ---------------- problem dims (fixed by dataset) ----------------
#define Bx 1024
#define TT 256
#define II 64
#define UU 1024
#define NN 4096            // 4*UU gate columns (interleaved n' = 4u+g)
#define KK (II + UU)       // 1088
// ---------------- tiling ----------------
#define MT  128            // M tile (batch rows per CTA)
#define NTL 256            // N tile (gate cols per CTA) = 64 units
#define KC  64             // K chunk per stage
#define NSTG (KK / KC)     // 17
#define NTHR 256           // 8 warps
#define ZS_STRIDE 260      // z SMEM row stride (floats), 16B-aligned rows

typedef __nv_bfloat16 bf16;
typedef unsigned int u32;
typedef unsigned long long u64;

// ---------------- device state (no allocation allowed) ----------------
__device__ bf16 g_Wt_hi[NN * KK];        // W^T, gate-interleaved, K-major
__device__ bf16 g_Wt_lo[NN * KK];
__device__ bf16 g_x_hi[Bx * TT * II];
__device__ bf16 g_x_lo[Bx * TT * II];
__device__ bf16 g_h_hi[2 * Bx * UU];     // double-buffered hidden state
__device__ bf16 g_h_lo[2 * Bx * UU];
__device__ float g_c[Bx * UU];
__device__ bf16 g_p_hi[Bx * II];         // fed-back prediction
__device__ bf16 g_p_lo[Bx * II];

// ---------------- helpers ----------------
__device__ __forceinline__ u32 smem_u32(const void* p) {
    u32 a;
    asm("{ .reg .u64 t; cvta.to.shared.u64 t, %1; cvt.u32.u64 %0, t; }" : "=r"(a) : "l"(p));
    return a;
}
#define SWZ(o) ((o) ^ ((((u32)(o)) >> 3) & 0x70))

__device__ __forceinline__ void cp16(u32 dst, const void* src) {
    asm volatile("cp.async.cg.shared.global [%0], [%1], 16;\n" :: "r"(dst), "l"(src) : "memory");
}
__device__ __forceinline__ void cp_commit() {
    asm volatile("cp.async.commit_group;\n" ::: "memory");
}
template<int N> __device__ __forceinline__ void cp_wait() {
    asm volatile("cp.async.wait_group %0;\n" :: "n"(N) : "memory");
}
__device__ __forceinline__ void ldsm4(u32* r, u32 addr) {
    asm volatile("ldmatrix.sync.aligned.m8n8.x4.shared.b16 {%0,%1,%2,%3}, [%4];"
                 : "=r"(r[0]), "=r"(r[1]), "=r"(r[2]), "=r"(r[3]) : "r"(addr));
}
__device__ __forceinline__ void mma16816(float* c, const u32* a, const u32* b) {
    asm volatile("mma.sync.aligned.m16n8k16.row.col.f32.bf16.bf16.f32 "
                 "{%0,%1,%2,%3}, {%4,%5,%6,%7}, {%8,%9}, {%0,%1,%2,%3};"
                 : "+f"(c[0]), "+f"(c[1]), "+f"(c[2]), "+f"(c[3])
                 : "r"(a[0]), "r"(a[1]), "r"(a[2]), "r"(a[3]), "r"(b[0]), "r"(b[1]));
}
__device__ __forceinline__ float sigm(float z)  { return 1.0f / (1.0f + __expf(-z)); }
__device__ __forceinline__ float tanhfast(float z) { return 2.0f / (1.0f + __expf(-2.0f * z)) - 1.0f; }

// ---------------- prep kernels (once per launch) ----------------
__global__ void prep_weights(const float* __restrict__ Wk, const float* __restrict__ Wr) {
    const int np = blockIdx.x;               // n' = 4u+g, 0..4095
    const int u = np >> 2, g = np & 3;
    const int col = g * UU + u;
    for (int k = threadIdx.x; k < KK; k += blockDim.x) {
        float w = (k < II) ? Wk[(size_t)k * NN + col] : Wr[(size_t)(k - II) * NN + col];
        bf16 hi = __float2bfloat16_rn(w);
        bf16 lo = __float2bfloat16_rn(w - __bfloat162float(hi));
        g_Wt_hi[(size_t)np * KK + k] = hi;
        g_Wt_lo[(size_t)np * KK + k] = lo;
    }
}
__global__ void prep_inputs(const float* __restrict__ x) {
    size_t i = (size_t)blockIdx.x * blockDim.x + threadIdx.x;
    if (i >= (size_t)Bx * TT * II) return;
    float v = x[i];
    bf16 hi = __float2bfloat16_rn(v);
    g_x_hi[i] = hi;
    g_x_lo[i] = __float2bfloat16_rn(v - __bfloat162float(hi));
}

// ---------------- LSTM step via mma.sync (HMMA) ----------------
// grid (NN/NTL, Bx/MT) = (16, 8). 256 thr = 8 warps, warp grid 2(M) x 4(N),
// warp tile 64x64. Split bf16: z = Ah*Bh + Ah*Bl + Al*Bh, fp32 accum.
__global__ __launch_bounds__(NTHR, 1)
void lstm_step_mma(const bf16* __restrict__ xh, const bf16* __restrict__ xl, int x_ld,
                   const bf16* __restrict__ hh, const bf16* __restrict__ hl,
                   bf16* __restrict__ oh, bf16* __restrict__ ol,
                   float* __restrict__ c, const float* __restrict__ bias)
{
    extern __shared__ char dynsmem[];
    __shared__ float s_bias[NTL];

    // 1024-align the working base (generic + shared-space views)
    char* smg = dynsmem + ((1024 - ((uintptr_t)dynsmem & 1023)) & 1023);
    const u32 base = smem_u32(smg);

    const int tid  = threadIdx.x;
    const int wid  = tid >> 5;
    const int lane = tid & 31;
    const int ni = blockIdx.x, mi = blockIdx.y;
    const int b0 = mi * MT;
    const int n0 = ni * NTL;
    const int u0 = ni * 64;
    const int wm = (wid >> 2) * 64;          // warp M offset
    const int wn = (wid & 3) * 64;           // warp N offset

    // stage buffer offsets: per buf 96KB = Ah(16K) Al(16K) Bh(32K) Bl(32K)
    #define AT(bf, p) (base + (bf) * 98304u + (p) * 16384u)
    #define BT(bf, p) (base + (bf) * 98304u + 32768u + (p) * 32768u)

    if (tid < NTL) s_bias[tid] = bias[(tid & 3) * UU + u0 + (tid >> 2)];

    float acc[4][8][4];
    #pragma unroll
    for (int m = 0; m < 4; m++)
        #pragma unroll
        for (int n = 0; n < 8; n++)
            #pragma unroll
            for (int q = 0; q < 4; q++) acc[m][n][q] = 0.0f;

    auto issue_loads = [&](int s, int buf) {
        const int kg = s * KC;
        const bf16 *Ah, *Al; int lda, ka;
        if (s == 0) { Ah = xh; Al = xl; lda = x_ld; ka = 0; }
        else        { Ah = hh; Al = hl; lda = UU;   ka = kg - II; }
        #pragma unroll
        for (int p = 0; p < 2; p++) {
            const bf16* src = p ? Al : Ah;
            #pragma unroll
            for (int i = 0; i < 4; i++) {            // 128 rows x 8 chunks / 256
                int idx = tid + i * NTHR;
                int row = idx >> 3, q = idx & 7;
                cp16(AT(buf, p) + SWZ(row * 128 + q * 16),
                     src + (size_t)(b0 + row) * lda + ka + q * 8);
            }
        }
        #pragma unroll
        for (int p = 0; p < 2; p++) {
            const bf16* src = p ? g_Wt_lo : g_Wt_hi;
            #pragma unroll
            for (int i = 0; i < 8; i++) {            // 256 rows x 8 chunks / 256
                int idx = tid + i * NTHR;
                int row = idx >> 3, q = idx & 7;
                cp16(BT(buf, p) + SWZ(row * 128 + q * 16),
                     src + (size_t)(n0 + row) * KK + kg + q * 8);
            }
        }
        cp_commit();
    };

    issue_loads(0, 0);

    for (int t = 0; t < NSTG; t++) {
        const int buf = t & 1;
        if (t + 1 < NSTG) { issue_loads(t + 1, buf ^ 1); cp_wait<1>(); }
        else              { cp_wait<0>(); }
        __syncthreads();

        #pragma unroll
        for (int kk = 0; kk < 4; kk++) {
            // A-hi fragments: 4 x m16k16
            u32 ah[4][4];
            #pragma unroll
            for (int m = 0; m < 4; m++) {
                int row = wm + m * 16 + (lane & 15);
                ldsm4(ah[m], AT(buf, 0) + SWZ(row * 128 + kk * 32 + (lane >> 4) * 16));
            }
            // B-hi fragments: 8 x n8k16 (pairs via x4)
            u32 bh[8][2];
            #pragma unroll
            for (int nf = 0; nf < 8; nf += 2) {
                int n = wn + nf * 8 + (lane >> 4) * 8 + (lane & 7);
                u32 r[4];
                ldsm4(r, BT(buf, 0) + SWZ(n * 128 + kk * 32 + ((lane >> 3) & 1) * 16));
                bh[nf][0] = r[0]; bh[nf][1] = r[1];
                bh[nf + 1][0] = r[2]; bh[nf + 1][1] = r[3];
            }
            #pragma unroll
            for (int m = 0; m < 4; m++)
                #pragma unroll
                for (int n = 0; n < 8; n++) mma16816(acc[m][n], ah[m], bh[n]);

            // B-lo: Ah * Bl
            #pragma unroll
            for (int nf = 0; nf < 8; nf += 2) {
                int n = wn + nf * 8 + (lane >> 4) * 8 + (lane & 7);
                u32 r[4];
                ldsm4(r, BT(buf, 1) + SWZ(n * 128 + kk * 32 + ((lane >> 3) & 1) * 16));
                u32 b0f[2] = { r[0], r[1] }, b1f[2] = { r[2], r[3] };
                #pragma unroll
                for (int m = 0; m < 4; m++) {
                    mma16816(acc[m][nf],     ah[m], b0f);
                    mma16816(acc[m][nf + 1], ah[m], b1f);
                }
            }
            // A-lo: Al * Bh
            #pragma unroll
            for (int m = 0; m < 4; m++) {
                int row = wm + m * 16 + (lane & 15);
                u32 al[4];
                ldsm4(al, AT(buf, 1) + SWZ(row * 128 + kk * 32 + (lane >> 4) * 16));
                #pragma unroll
                for (int n = 0; n < 8; n++) mma16816(acc[m][n], al, bh[n]);
            }
        }
        __syncthreads();   // stage bufs free for the next prefetch
    }

    // ---------------- epilogue: accums -> SMEM -> gate math -> c,h ----------------
    float* zs = (float*)smg;   // 128 x ZS_STRIDE fp32 = 133KB, reuses stage bufs
    #pragma unroll
    for (int m = 0; m < 4; m++) {
        int row = wm + m * 16 + (lane >> 2);
        #pragma unroll
        for (int n = 0; n < 8; n++) {
            int col = wn + n * 8 + (lane & 3) * 2;
            *(float2*)&zs[row * ZS_STRIDE + col]       = make_float2(acc[m][n][0], acc[m][n][1]);
            *(float2*)&zs[(row + 8) * ZS_STRIDE + col] = make_float2(acc[m][n][2], acc[m][n][3]);
        }
    }
    __syncthreads();

    #pragma unroll 1
    for (int it = 0; it < (MT * 64) / NTHR; it++) {    // 32 iterations
        int idx = tid + it * NTHR;
        int row = idx >> 6;            // 0..127
        int ul  = idx & 63;            // unit within tile
        float4 z = *(const float4*)&zs[row * ZS_STRIDE + 4 * ul];
        float zi = z.x + s_bias[4 * ul + 0];
        float zf = z.y + s_bias[4 * ul + 1];
        float zg = z.z + s_bias[4 * ul + 2];
        float zo = z.w + s_bias[4 * ul + 3];

        const size_t gidx = (size_t)(b0 + row) * UU + u0 + ul;
        float cv = c[gidx];
        float cn = sigm(zf) * cv + sigm(zi) * tanhfast(zg);
        c[gidx] = cn;
        float hv = sigm(zo) * tanhfast(cn);

        bf16 hhi = __float2bfloat16_rn(hv);
        oh[gidx] = hhi;
        ol[gidx] = __float2bfloat16_rn(hv - __bfloat162float(hhi));
    }
    #undef AT
    #undef BT
}

// ---------------- dense head ----------------
__global__ __launch_bounds__(64) void dense_kernel(
    const bf16* __restrict__ hh, const bf16* __restrict__ hl,
    const float* __restrict__ Wd, const float* __restrict__ bd,
    const int* __restrict__ oidx, int n_idx,
    bf16* __restrict__ ph, bf16* __restrict__ pl,
    float* __restrict__ out, int s, int S)
{
    __shared__ float hs[UU];
    __shared__ float ps[II];
    const int b = blockIdx.x;
    const int i = threadIdx.x;

    for (int k = i; k < UU; k += 64)
        hs[k] = __bfloat162float(hh[(size_t)b * UU + k]) + __bfloat162float(hl[(size_t)b * UU + k]);
    __syncthreads();

    float acc = bd[i];
    #pragma unroll 8
    for (int u = 0; u < UU; u++)
        acc += hs[u] * Wd[u * II + i];

    bf16 hi = __float2bfloat16_rn(acc);
    ph[(size_t)b * II + i] = hi;
    pl[(size_t)b * II + i] = __float2bfloat16_rn(acc - __bfloat162float(hi));
    ps[i] = acc;
    __syncthreads();
    if (i < n_idx)
        out[((size_t)b * S + s) * n_idx + i] = ps[oidx[i]];
}

// ---------------- host driver ----------------
extern "C" void kernel_launch(void* const* d_in, const int* in_sizes, int n_in,
                              void* d_out, int out_size)
{
    const float* inputs = (const float*)d_in[0];
    const float* Wk     = (const float*)d_in[1];
    const float* Wr     = (const float*)d_in[2];
    const float* bias   = (const float*)d_in[3];
    const float* Wd     = (const float*)d_in[4];
    const float* bd     = (const float*)d_in[5];
    const int*   oidx   = (const int*)d_in[6];
    float*       out    = (float*)d_out;

    const int n_idx = in_sizes[6];
    const int S     = out_size / (Bx * n_idx);

    bf16 *xh, *xl, *hh, *hl, *ph, *pl;
    float *cb;
    cudaGetSymbolAddress((void**)&xh, g_x_hi);
    cudaGetSymbolAddress((void**)&xl, g_x_lo);
    cudaGetSymbolAddress((void**)&hh, g_h_hi);
    cudaGetSymbolAddress((void**)&hl, g_h_lo);
    cudaGetSymbolAddress((void**)&cb, g_c);
    cudaGetSymbolAddress((void**)&ph, g_p_hi);
    cudaGetSymbolAddress((void**)&pl, g_p_lo);

    const int dyn_smem = 2 * 98304 + 1024;   // 197632 B
    cudaFuncSetAttribute(lstm_step_mma, cudaFuncAttributeMaxDynamicSharedMemorySize, dyn_smem);

    // one-time-per-launch prep
    prep_weights<<<NN, 256>>>(Wk, Wr);
    prep_inputs<<<(Bx * TT * II) / 256, 256>>>(inputs);
    cudaMemsetAsync(hh, 0, sizeof(bf16) * Bx * UU);
    cudaMemsetAsync(hl, 0, sizeof(bf16) * Bx * UU);
    cudaMemsetAsync(cb, 0, sizeof(float) * Bx * UU);

    const dim3 grid(NN / NTL, Bx / MT);      // (16, 8) = 128 CTAs, single wave
    int cur = 0;

    for (int t = 0; t < TT; t++) {
        lstm_step_mma<<<grid, NTHR, dyn_smem>>>(
            xh + (size_t)t * II, xl + (size_t)t * II, TT * II,
            hh + (size_t)cur * Bx * UU, hl + (size_t)cur * Bx * UU,
            hh + (size_t)(cur ^ 1) * Bx * UU, hl + (size_t)(cur ^ 1) * Bx * UU,
            cb, bias);
        cur ^= 1;
    }

    dense_kernel<<<Bx, 64>>>(hh + (size_t)cur * Bx * UU, hl + (size_t)cur * Bx * UU,
                             Wd, bd, oidx, n_idx, ph, pl, out, 0, S);

    for (int s = 1; s < S; s++) {
        lstm_step_mma<<<grid, NTHR, dyn_smem>>>(
            ph, pl, II,
            hh + (size_t)cur * Bx * UU, hl + (size_t)cur * Bx * UU,
            hh + (size_t)(cur ^ 1) * Bx * UU, hl + (size_t)(cur ^ 1) * Bx * UU,
            cb, bias);
        cur ^= 1;
        dense_kernel<<<Bx, 64>>>(hh + (size_t)cur * Bx * UU, hl + (size_t)cur * Bx * UU,
                                 Wd, bd, oidx, n_idx, ph, pl, out, s, S);
    }
}

// round 7
// speedup vs baseline: 3.6429x; 1.0447x over previous
#include <cuda_runtime.h>
#include <cuda_bf16.h>
#include <cstdint>
#include <math.h>

// ---------------- problem dims (fixed by dataset) ----------------
#define Bx 1024
#define TT 256
#define II 64
#define UU 1024
#define NN 4096            // 4*UU gate columns (interleaved n' = 4u+g)
#define KK (II + UU)       // 1088 (warmup), decode K = UU = 1024
// ---------------- tiling ----------------
#define MT  128            // M tile (batch rows per CTA)
#define NTL 256            // N tile (gate cols per CTA) = 64 units
#define KC  64             // K chunk per stage
#define NTHR 512           // 16 warps, warp grid 4(M) x 4(N), warp tile 32x64
#define ZS_STRIDE 260      // z SMEM row stride (floats)

typedef __nv_bfloat16 bf16;
typedef unsigned int u32;

// ---------------- device state (no allocation allowed) ----------------
__device__ bf16 g_Wt_hi[NN * KK];        // warmup W^T, gate-interleaved, K-major
__device__ bf16 g_Wt_lo[NN * KK];
__device__ bf16 g_W2_hi[NN * UU];        // decode W'^T = (Wr + Wd@Wk)^T interleaved
__device__ bf16 g_W2_lo[NN * UU];
__device__ float g_b2[NN];               // b' = b + bd@Wk (gate-major)
__device__ bf16 g_x_hi[Bx * TT * II];
__device__ bf16 g_x_lo[Bx * TT * II];
__device__ bf16 g_h_hi[2 * Bx * UU];     // double-buffered hidden state
__device__ bf16 g_h_lo[2 * Bx * UU];
__device__ float g_c[Bx * UU];

// ---------------- helpers ----------------
__device__ __forceinline__ u32 smem_u32(const void* p) {
    u32 a;
    asm("{ .reg .u64 t; cvta.to.shared.u64 t, %1; cvt.u32.u64 %0, t; }" : "=r"(a) : "l"(p));
    return a;
}
#define SWZ(o) ((o) ^ ((((u32)(o)) >> 3) & 0x70))

__device__ __forceinline__ void cp16(u32 dst, const void* src) {
    asm volatile("cp.async.cg.shared.global [%0], [%1], 16;\n" :: "r"(dst), "l"(src) : "memory");
}
__device__ __forceinline__ void cp_commit() {
    asm volatile("cp.async.commit_group;\n" ::: "memory");
}
template<int N> __device__ __forceinline__ void cp_wait() {
    asm volatile("cp.async.wait_group %0;\n" :: "n"(N) : "memory");
}
__device__ __forceinline__ void ldsm4(u32* r, u32 addr) {
    asm volatile("ldmatrix.sync.aligned.m8n8.x4.shared.b16 {%0,%1,%2,%3}, [%4];"
                 : "=r"(r[0]), "=r"(r[1]), "=r"(r[2]), "=r"(r[3]) : "r"(addr));
}
__device__ __forceinline__ void mma16816(float* c, const u32* a, const u32* b) {
    asm volatile("mma.sync.aligned.m16n8k16.row.col.f32.bf16.bf16.f32 "
                 "{%0,%1,%2,%3}, {%4,%5,%6,%7}, {%8,%9}, {%0,%1,%2,%3};"
                 : "+f"(c[0]), "+f"(c[1]), "+f"(c[2]), "+f"(c[3])
                 : "r"(a[0]), "r"(a[1]), "r"(a[2]), "r"(a[3]), "r"(b[0]), "r"(b[1]));
}
__device__ __forceinline__ float sigm(float z)  { return 1.0f / (1.0f + __expf(-z)); }
__device__ __forceinline__ float tanhfast(float z) { return 2.0f / (1.0f + __expf(-2.0f * z)) - 1.0f; }

// ---------------- prep kernels (once per launch) ----------------
// Warmup W^T (gate-interleaved n' = 4u+g), split bf16 hi/lo.
__global__ void prep_weights(const float* __restrict__ Wk, const float* __restrict__ Wr) {
    const int np = blockIdx.x;
    const int u = np >> 2, g = np & 3;
    const int col = g * UU + u;
    for (int k = threadIdx.x; k < KK; k += blockDim.x) {
        float w = (k < II) ? Wk[(size_t)k * NN + col] : Wr[(size_t)(k - II) * NN + col];
        bf16 hi = __float2bfloat16_rn(w);
        g_Wt_hi[(size_t)np * KK + k] = hi;
        g_Wt_lo[(size_t)np * KK + k] = __float2bfloat16_rn(w - __bfloat162float(hi));
    }
}
// Decode W'^T = (Wr + Wd@Wk)^T and b' = b + bd@Wk.
__global__ void prep_w2(const float* __restrict__ Wk, const float* __restrict__ Wr,
                        const float* __restrict__ Wd, const float* __restrict__ b,
                        const float* __restrict__ bd) {
    __shared__ float wkcol[II];
    const int np = blockIdx.x;
    const int u = np >> 2, g = np & 3;
    const int col = g * UU + u;
    if (threadIdx.x < II) wkcol[threadIdx.x] = Wk[(size_t)threadIdx.x * NN + col];
    __syncthreads();
    for (int k = threadIdx.x; k < UU; k += blockDim.x) {
        float w = Wr[(size_t)k * NN + col];
        #pragma unroll 16
        for (int i = 0; i < II; i++) w += Wd[(size_t)k * II + i] * wkcol[i];
        bf16 hi = __float2bfloat16_rn(w);
        g_W2_hi[(size_t)np * UU + k] = hi;
        g_W2_lo[(size_t)np * UU + k] = __float2bfloat16_rn(w - __bfloat162float(hi));
    }
    if (threadIdx.x == 0) {
        float bb = b[col];
        for (int i = 0; i < II; i++) bb += bd[i] * wkcol[i];
        g_b2[col] = bb;
    }
}
__global__ void prep_inputs(const float* __restrict__ x) {
    size_t i = (size_t)blockIdx.x * blockDim.x + threadIdx.x;
    if (i >= (size_t)Bx * TT * II) return;
    float v = x[i];
    bf16 hi = __float2bfloat16_rn(v);
    g_x_hi[i] = hi;
    g_x_lo[i] = __float2bfloat16_rn(v - __bfloat162float(hi));
}

// ---------------- LSTM step via mma.sync (HMMA), split bf16 hi/lo ----------------
// grid (16, 8) = 128 CTAs. 512 thr = 16 warps, warp grid 4(M) x 4(N), tile 32x64.
// z = Ah*Bh + Ah*Bl + Al*Bh, fp32 accum. nstg stages of KC=64.
__global__ __launch_bounds__(NTHR, 1)
void lstm_step_mma(const bf16* __restrict__ xh, const bf16* __restrict__ xl,
                   int x_ld, int first_is_x,
                   const bf16* __restrict__ hh, const bf16* __restrict__ hl,
                   const bf16* __restrict__ wth, const bf16* __restrict__ wtl, int wt_k,
                   bf16* __restrict__ oh, bf16* __restrict__ ol,
                   float* __restrict__ c, const float* __restrict__ bias, int nstg)
{
    extern __shared__ char dynsmem[];
    __shared__ float s_bias[NTL];

    char* smg = dynsmem + ((1024 - ((uintptr_t)dynsmem & 1023)) & 1023);
    const u32 base = smem_u32(smg);

    const int tid  = threadIdx.x;
    const int wid  = tid >> 5;
    const int lane = tid & 31;
    const int ni = blockIdx.x, mi = blockIdx.y;
    const int b0 = mi * MT;
    const int n0 = ni * NTL;
    const int u0 = ni * 64;
    const int wm = (wid >> 2) * 32;          // warp M offset (4 x 32 = 128)
    const int wn = (wid & 3) * 64;           // warp N offset (4 x 64 = 256)

    // stage buffers: per buf 96KB = Ah(16K) Al(16K) Bh(32K) Bl(32K)
    #define AT(bf, p) (base + (bf) * 98304u + (p) * 16384u)
    #define BT(bf, p) (base + (bf) * 98304u + 32768u + (p) * 32768u)

    if (tid < NTL) s_bias[tid] = bias[(tid & 3) * UU + u0 + (tid >> 2)];

    float acc[2][8][4];
    #pragma unroll
    for (int m = 0; m < 2; m++)
        #pragma unroll
        for (int n = 0; n < 8; n++)
            #pragma unroll
            for (int q = 0; q < 4; q++) acc[m][n][q] = 0.0f;

    auto issue_loads = [&](int s, int buf) {
        const int kg = s * KC;
        const bf16 *Ah, *Al; int lda, ka;
        if (first_is_x && s == 0) { Ah = xh; Al = xl; lda = x_ld; ka = 0; }
        else { Ah = hh; Al = hl; lda = UU; ka = kg - (first_is_x ? II : 0); }
        #pragma unroll
        for (int p = 0; p < 2; p++) {
            const bf16* src = p ? Al : Ah;
            #pragma unroll
            for (int i = 0; i < 2; i++) {            // 1024 chunks / 512 thr
                int idx = tid + i * NTHR;
                int row = idx >> 3, q = idx & 7;
                cp16(AT(buf, p) + SWZ(row * 128 + q * 16),
                     src + (size_t)(b0 + row) * lda + ka + q * 8);
            }
        }
        #pragma unroll
        for (int p = 0; p < 2; p++) {
            const bf16* src = p ? wtl : wth;
            #pragma unroll
            for (int i = 0; i < 4; i++) {            // 2048 chunks / 512 thr
                int idx = tid + i * NTHR;
                int row = idx >> 3, q = idx & 7;
                cp16(BT(buf, p) + SWZ(row * 128 + q * 16),
                     src + (size_t)(n0 + row) * wt_k + kg + q * 8);
            }
        }
        cp_commit();
    };

    issue_loads(0, 0);

    for (int t = 0; t < nstg; t++) {
        const int buf = t & 1;
        if (t + 1 < nstg) { issue_loads(t + 1, buf ^ 1); cp_wait<1>(); }
        else              { cp_wait<0>(); }
        __syncthreads();

        #pragma unroll
        for (int kk = 0; kk < 4; kk++) {
            // A-hi: 2 x m16k16 fragments
            u32 ah[2][4];
            #pragma unroll
            for (int m = 0; m < 2; m++) {
                int row = wm + m * 16 + (lane & 15);
                ldsm4(ah[m], AT(buf, 0) + SWZ(row * 128 + kk * 32 + (lane >> 4) * 16));
            }
            // B-hi: 8 x n8k16 fragments (pairs via x4)
            u32 bh[8][2];
            #pragma unroll
            for (int nf = 0; nf < 8; nf += 2) {
                int n = wn + nf * 8 + (lane >> 4) * 8 + (lane & 7);
                u32 r[4];
                ldsm4(r, BT(buf, 0) + SWZ(n * 128 + kk * 32 + ((lane >> 3) & 1) * 16));
                bh[nf][0] = r[0]; bh[nf][1] = r[1];
                bh[nf + 1][0] = r[2]; bh[nf + 1][1] = r[3];
            }
            #pragma unroll
            for (int m = 0; m < 2; m++)
                #pragma unroll
                for (int n = 0; n < 8; n++) mma16816(acc[m][n], ah[m], bh[n]);

            // Ah * Bl
            #pragma unroll
            for (int nf = 0; nf < 8; nf += 2) {
                int n = wn + nf * 8 + (lane >> 4) * 8 + (lane & 7);
                u32 r[4];
                ldsm4(r, BT(buf, 1) + SWZ(n * 128 + kk * 32 + ((lane >> 3) & 1) * 16));
                u32 b0f[2] = { r[0], r[1] }, b1f[2] = { r[2], r[3] };
                #pragma unroll
                for (int m = 0; m < 2; m++) {
                    mma16816(acc[m][nf],     ah[m], b0f);
                    mma16816(acc[m][nf + 1], ah[m], b1f);
                }
            }
            // Al * Bh
            #pragma unroll
            for (int m = 0; m < 2; m++) {
                int row = wm + m * 16 + (lane & 15);
                u32 al[4];
                ldsm4(al, AT(buf, 1) + SWZ(row * 128 + kk * 32 + (lane >> 4) * 16));
                #pragma unroll
                for (int n = 0; n < 8; n++) mma16816(acc[m][n], al, bh[n]);
            }
        }
        __syncthreads();
    }

    // ---------------- epilogue: accums -> SMEM -> gate math -> c,h ----------------
    float* zs = (float*)smg;   // 128 x ZS_STRIDE fp32, reuses stage bufs
    #pragma unroll
    for (int m = 0; m < 2; m++) {
        int row = wm + m * 16 + (lane >> 2);
        #pragma unroll
        for (int n = 0; n < 8; n++) {
            int col = wn + n * 8 + (lane & 3) * 2;
            *(float2*)&zs[row * ZS_STRIDE + col]       = make_float2(acc[m][n][0], acc[m][n][1]);
            *(float2*)&zs[(row + 8) * ZS_STRIDE + col] = make_float2(acc[m][n][2], acc[m][n][3]);
        }
    }
    __syncthreads();

    #pragma unroll 1
    for (int it = 0; it < (MT * 64) / NTHR; it++) {    // 16 iterations
        int idx = tid + it * NTHR;
        int row = idx >> 6;
        int ul  = idx & 63;
        float4 z = *(const float4*)&zs[row * ZS_STRIDE + 4 * ul];
        float zi = z.x + s_bias[4 * ul + 0];
        float zf = z.y + s_bias[4 * ul + 1];
        float zg = z.z + s_bias[4 * ul + 2];
        float zo = z.w + s_bias[4 * ul + 3];

        const size_t gidx = (size_t)(b0 + row) * UU + u0 + ul;
        float cv = c[gidx];
        float cn = sigm(zf) * cv + sigm(zi) * tanhfast(zg);
        c[gidx] = cn;
        float hv = sigm(zo) * tanhfast(cn);

        bf16 hhi = __float2bfloat16_rn(hv);
        oh[gidx] = hhi;
        ol[gidx] = __float2bfloat16_rn(hv - __bfloat162float(hhi));
    }
    #undef AT
    #undef BT
}

// ---------------- output kernel: only the indexed columns of pred ----------------
// out[b, s, j] = sum_u h[b,u] * Wd[u, oidx[j]] + bd[oidx[j]]
__global__ __launch_bounds__(256) void out_kernel(
    const bf16* __restrict__ hh, const bf16* __restrict__ hl,
    const float* __restrict__ Wd, const float* __restrict__ bd,
    const int* __restrict__ oidx, int n_idx,
    float* __restrict__ out, int s, int S)
{
    const int wid  = threadIdx.x >> 5;
    const int lane = threadIdx.x & 31;
    const int b = blockIdx.x * 8 + wid;

    float a0 = 0.0f, a1 = 0.0f;                       // n_idx <= 2 fast path
    const int o0 = oidx[0];
    const int o1 = (n_idx > 1) ? oidx[1] : 0;
    #pragma unroll 4
    for (int i = 0; i < UU / 32; i++) {
        int u = lane + i * 32;
        float hv = __bfloat162float(hh[(size_t)b * UU + u])
                 + __bfloat162float(hl[(size_t)b * UU + u]);
        a0 += hv * Wd[(size_t)u * II + o0];
        a1 += hv * Wd[(size_t)u * II + o1];
    }
    #pragma unroll
    for (int off = 16; off > 0; off >>= 1) {
        a0 += __shfl_down_sync(0xFFFFFFFFu, a0, off);
        a1 += __shfl_down_sync(0xFFFFFFFFu, a1, off);
    }
    if (lane == 0) {
        out[((size_t)b * S + s) * n_idx + 0] = a0 + bd[o0];
        if (n_idx > 1) out[((size_t)b * S + s) * n_idx + 1] = a1 + bd[o1];
    }
}

// ---------------- host driver ----------------
extern "C" void kernel_launch(void* const* d_in, const int* in_sizes, int n_in,
                              void* d_out, int out_size)
{
    const float* inputs = (const float*)d_in[0];
    const float* Wk     = (const float*)d_in[1];
    const float* Wr     = (const float*)d_in[2];
    const float* bias   = (const float*)d_in[3];
    const float* Wd     = (const float*)d_in[4];
    const float* bd     = (const float*)d_in[5];
    const int*   oidx   = (const int*)d_in[6];
    float*       out    = (float*)d_out;

    const int n_idx = in_sizes[6];
    const int S     = out_size / (Bx * n_idx);

    bf16 *xh, *xl, *hh, *hl, *wth, *wtl, *w2h, *w2l;
    float *cb, *b2;
    cudaGetSymbolAddress((void**)&xh, g_x_hi);
    cudaGetSymbolAddress((void**)&xl, g_x_lo);
    cudaGetSymbolAddress((void**)&hh, g_h_hi);
    cudaGetSymbolAddress((void**)&hl, g_h_lo);
    cudaGetSymbolAddress((void**)&cb, g_c);
    cudaGetSymbolAddress((void**)&wth, g_Wt_hi);
    cudaGetSymbolAddress((void**)&wtl, g_Wt_lo);
    cudaGetSymbolAddress((void**)&w2h, g_W2_hi);
    cudaGetSymbolAddress((void**)&w2l, g_W2_lo);
    cudaGetSymbolAddress((void**)&b2, g_b2);

    const int dyn_smem = 2 * 98304 + 1024;   // 197632 B
    cudaFuncSetAttribute(lstm_step_mma, cudaFuncAttributeMaxDynamicSharedMemorySize, dyn_smem);

    // one-time-per-launch prep
    prep_weights<<<NN, 256>>>(Wk, Wr);
    prep_w2<<<NN, 256>>>(Wk, Wr, Wd, bias, bd);
    prep_inputs<<<(Bx * TT * II) / 256, 256>>>(inputs);
    cudaMemsetAsync(hh, 0, sizeof(bf16) * Bx * UU);
    cudaMemsetAsync(hl, 0, sizeof(bf16) * Bx * UU);
    cudaMemsetAsync(cb, 0, sizeof(float) * Bx * UU);

    const dim3 grid(NN / NTL, Bx / MT);      // (16, 8) = 128 CTAs, single wave
    int cur = 0;

    // warmup: 256 steps, K = 1088 (x chunk + h)
    for (int t = 0; t < TT; t++) {
        lstm_step_mma<<<grid, NTHR, dyn_smem>>>(
            xh + (size_t)t * II, xl + (size_t)t * II, TT * II, 1,
            hh + (size_t)cur * Bx * UU, hl + (size_t)cur * Bx * UU,
            wth, wtl, KK,
            hh + (size_t)(cur ^ 1) * Bx * UU, hl + (size_t)(cur ^ 1) * Bx * UU,
            cb, bias, KK / KC);
        cur ^= 1;
    }

    out_kernel<<<Bx / 8, 256>>>(hh + (size_t)cur * Bx * UU, hl + (size_t)cur * Bx * UU,
                                Wd, bd, oidx, n_idx, out, 0, S);

    // decode: folded weights, K = 1024, no feedback kernel in the chain
    for (int s = 1; s < S; s++) {
        lstm_step_mma<<<grid, NTHR, dyn_smem>>>(
            (const bf16*)0, (const bf16*)0, 0, 0,
            hh + (size_t)cur * Bx * UU, hl + (size_t)cur * Bx * UU,
            w2h, w2l, UU,
            hh + (size_t)(cur ^ 1) * Bx * UU, hl + (size_t)(cur ^ 1) * Bx * UU,
            cb, b2, UU / KC);
        cur ^= 1;
        out_kernel<<<Bx / 8, 256>>>(hh + (size_t)cur * Bx * UU, hl + (size_t)cur * Bx * UU,
                                    Wd, bd, oidx, n_idx, out, s, S);
    }
}

// round 8
// speedup vs baseline: 5.1083x; 1.4022x over previous
#include <cuda_runtime.h>
#include <cuda_fp16.h>
#include <cstdint>
#include <math.h>

// ---------------- problem dims (fixed by dataset) ----------------
#define Bx 1024
#define TT 256
#define II 64
#define UU 1024
#define NN 4096            // 4*UU gate columns (interleaved n' = 4u+g)
#define KK (II + UU)       // 1088 (warmup), decode K = UU = 1024
// ---------------- tiling ----------------
#define MT  128            // M tile (batch rows per CTA)
#define NTL 256            // N tile (gate cols per CTA) = 64 units
#define KC  64             // K chunk per stage (128B rows, SW128)
#define NTHR 512           // 16 warps, warp grid 4(M) x 4(N), warp tile 32x64
#define ZS_STRIDE 260      // z SMEM row stride (floats)

typedef __half f16;
typedef unsigned int u32;

// ---------------- device state (no allocation allowed) ----------------
__device__ f16 g_Wt_hi[NN * KK];        // warmup W^T, gate-interleaved, K-major
__device__ f16 g_Wt_lo[NN * KK];
__device__ f16 g_W2_hi[NN * UU];        // decode W'^T = (Wr + Wd@Wk)^T interleaved
__device__ f16 g_W2_lo[NN * UU];
__device__ float g_b2[NN];              // b' = b + bd@Wk (gate-major)
__device__ f16 g_x[Bx * TT * II];       // inputs, single fp16
__device__ f16 g_h[2 * Bx * UU];        // double-buffered hidden state, single fp16
__device__ float g_c[Bx * UU];

// ---------------- helpers ----------------
__device__ __forceinline__ u32 smem_u32(const void* p) {
    u32 a;
    asm("{ .reg .u64 t; cvta.to.shared.u64 t, %1; cvt.u32.u64 %0, t; }" : "=r"(a) : "l"(p));
    return a;
}
#define SWZ(o) ((o) ^ ((((u32)(o)) >> 3) & 0x70))

__device__ __forceinline__ void cp16(u32 dst, const void* src) {
    asm volatile("cp.async.cg.shared.global [%0], [%1], 16;\n" :: "r"(dst), "l"(src) : "memory");
}
__device__ __forceinline__ void cp_commit() {
    asm volatile("cp.async.commit_group;\n" ::: "memory");
}
template<int N> __device__ __forceinline__ void cp_wait() {
    asm volatile("cp.async.wait_group %0;\n" :: "n"(N) : "memory");
}
__device__ __forceinline__ void ldsm4(u32* r, u32 addr) {
    asm volatile("ldmatrix.sync.aligned.m8n8.x4.shared.b16 {%0,%1,%2,%3}, [%4];"
                 : "=r"(r[0]), "=r"(r[1]), "=r"(r[2]), "=r"(r[3]) : "r"(addr));
}
__device__ __forceinline__ void mma16816(float* c, const u32* a, const u32* b) {
    asm volatile("mma.sync.aligned.m16n8k16.row.col.f32.f16.f16.f32 "
                 "{%0,%1,%2,%3}, {%4,%5,%6,%7}, {%8,%9}, {%0,%1,%2,%3};"
                 : "+f"(c[0]), "+f"(c[1]), "+f"(c[2]), "+f"(c[3])
                 : "r"(a[0]), "r"(a[1]), "r"(a[2]), "r"(a[3]), "r"(b[0]), "r"(b[1]));
}
__device__ __forceinline__ float sigm(float z)  { return 1.0f / (1.0f + __expf(-z)); }
__device__ __forceinline__ float tanhfast(float z) { return 2.0f / (1.0f + __expf(-2.0f * z)) - 1.0f; }

// ---------------- prep kernels (once per launch) ----------------
// Warmup W^T (gate-interleaved n' = 4u+g), split fp16 hi/lo.
__global__ void prep_weights(const float* __restrict__ Wk, const float* __restrict__ Wr) {
    const int np = blockIdx.x;
    const int u = np >> 2, g = np & 3;
    const int col = g * UU + u;
    for (int k = threadIdx.x; k < KK; k += blockDim.x) {
        float w = (k < II) ? Wk[(size_t)k * NN + col] : Wr[(size_t)(k - II) * NN + col];
        f16 hi = __float2half_rn(w);
        g_Wt_hi[(size_t)np * KK + k] = hi;
        g_Wt_lo[(size_t)np * KK + k] = __float2half_rn(w - __half2float(hi));
    }
}
// Decode W'^T = (Wr + Wd@Wk)^T and b' = b + bd@Wk.
__global__ void prep_w2(const float* __restrict__ Wk, const float* __restrict__ Wr,
                        const float* __restrict__ Wd, const float* __restrict__ b,
                        const float* __restrict__ bd) {
    __shared__ float wkcol[II];
    const int np = blockIdx.x;
    const int u = np >> 2, g = np & 3;
    const int col = g * UU + u;
    if (threadIdx.x < II) wkcol[threadIdx.x] = Wk[(size_t)threadIdx.x * NN + col];
    __syncthreads();
    for (int k = threadIdx.x; k < UU; k += blockDim.x) {
        float w = Wr[(size_t)k * NN + col];
        #pragma unroll 16
        for (int i = 0; i < II; i++) w += Wd[(size_t)k * II + i] * wkcol[i];
        f16 hi = __float2half_rn(w);
        g_W2_hi[(size_t)np * UU + k] = hi;
        g_W2_lo[(size_t)np * UU + k] = __float2half_rn(w - __half2float(hi));
    }
    if (threadIdx.x == 0) {
        float bb = b[col];
        for (int i = 0; i < II; i++) bb += bd[i] * wkcol[i];
        g_b2[col] = bb;
    }
}
__global__ void prep_inputs(const float* __restrict__ x) {
    size_t i = (size_t)blockIdx.x * blockDim.x + threadIdx.x;
    if (i >= (size_t)Bx * TT * II) return;
    g_x[i] = __float2half_rn(x[i]);
}

// ---------------- LSTM step via mma.sync (HMMA), fp16 2-term ----------------
// grid (16, 8) = 128 CTAs. 512 thr = 16 warps, warp grid 4(M) x 4(N), tile 32x64.
// z = A*Bh + A*Bl (A single fp16, B split fp16 hi/lo), fp32 accum.
__global__ __launch_bounds__(NTHR, 1)
void lstm_step_mma(const f16* __restrict__ xp, int x_ld, int first_is_x,
                   const f16* __restrict__ hp,
                   const f16* __restrict__ wth, const f16* __restrict__ wtl, int wt_k,
                   f16* __restrict__ op,
                   float* __restrict__ c, const float* __restrict__ bias, int nstg)
{
    extern __shared__ char dynsmem[];
    __shared__ float s_bias[NTL];

    char* smg = dynsmem + ((1024 - ((uintptr_t)dynsmem & 1023)) & 1023);
    const u32 base = smem_u32(smg);

    const int tid  = threadIdx.x;
    const int wid  = tid >> 5;
    const int lane = tid & 31;
    const int ni = blockIdx.x, mi = blockIdx.y;
    const int b0 = mi * MT;
    const int n0 = ni * NTL;
    const int u0 = ni * 64;
    const int wm = (wid >> 2) * 32;          // warp M offset (4 x 32 = 128)
    const int wn = (wid & 3) * 64;           // warp N offset (4 x 64 = 256)

    // stage buffers: per buf 80KB = A(16K) Bh(32K) Bl(32K)
    #define AT(bf)    (base + (bf) * 81920u)
    #define BT(bf, p) (base + (bf) * 81920u + 16384u + (p) * 32768u)

    if (tid < NTL) s_bias[tid] = bias[(tid & 3) * UU + u0 + (tid >> 2)];

    float acc[2][8][4];
    #pragma unroll
    for (int m = 0; m < 2; m++)
        #pragma unroll
        for (int n = 0; n < 8; n++)
            #pragma unroll
            for (int q = 0; q < 4; q++) acc[m][n][q] = 0.0f;

    auto issue_loads = [&](int s, int buf) {
        const int kg = s * KC;
        const f16* A; int lda, ka;
        if (first_is_x && s == 0) { A = xp; lda = x_ld; ka = 0; }
        else { A = hp; lda = UU; ka = kg - (first_is_x ? II : 0); }
        #pragma unroll
        for (int i = 0; i < 2; i++) {            // A: 1024 chunks / 512 thr
            int idx = tid + i * NTHR;
            int row = idx >> 3, q = idx & 7;
            cp16(AT(buf) + SWZ(row * 128 + q * 16),
                 A + (size_t)(b0 + row) * lda + ka + q * 8);
        }
        #pragma unroll
        for (int p = 0; p < 2; p++) {
            const f16* src = p ? wtl : wth;
            #pragma unroll
            for (int i = 0; i < 4; i++) {        // B: 2048 chunks per part / 512
                int idx = tid + i * NTHR;
                int row = idx >> 3, q = idx & 7;
                cp16(BT(buf, p) + SWZ(row * 128 + q * 16),
                     src + (size_t)(n0 + row) * wt_k + kg + q * 8);
            }
        }
        cp_commit();
    };

    issue_loads(0, 0);

    for (int t = 0; t < nstg; t++) {
        const int buf = t & 1;
        if (t + 1 < nstg) { issue_loads(t + 1, buf ^ 1); cp_wait<1>(); }
        else              { cp_wait<0>(); }
        __syncthreads();

        #pragma unroll
        for (int kk = 0; kk < 4; kk++) {
            // A: 2 x m16k16 fragments
            u32 ah[2][4];
            #pragma unroll
            for (int m = 0; m < 2; m++) {
                int row = wm + m * 16 + (lane & 15);
                ldsm4(ah[m], AT(buf) + SWZ(row * 128 + kk * 32 + (lane >> 4) * 16));
            }
            // B-hi: 8 x n8k16 fragments (pairs via x4)
            u32 bh[8][2];
            #pragma unroll
            for (int nf = 0; nf < 8; nf += 2) {
                int n = wn + nf * 8 + (lane >> 4) * 8 + (lane & 7);
                u32 r[4];
                ldsm4(r, BT(buf, 0) + SWZ(n * 128 + kk * 32 + ((lane >> 3) & 1) * 16));
                bh[nf][0] = r[0]; bh[nf][1] = r[1];
                bh[nf + 1][0] = r[2]; bh[nf + 1][1] = r[3];
            }
            #pragma unroll
            for (int m = 0; m < 2; m++)
                #pragma unroll
                for (int n = 0; n < 8; n++) mma16816(acc[m][n], ah[m], bh[n]);

            // A * B-lo
            #pragma unroll
            for (int nf = 0; nf < 8; nf += 2) {
                int n = wn + nf * 8 + (lane >> 4) * 8 + (lane & 7);
                u32 r[4];
                ldsm4(r, BT(buf, 1) + SWZ(n * 128 + kk * 32 + ((lane >> 3) & 1) * 16));
                u32 b0f[2] = { r[0], r[1] }, b1f[2] = { r[2], r[3] };
                #pragma unroll
                for (int m = 0; m < 2; m++) {
                    mma16816(acc[m][nf],     ah[m], b0f);
                    mma16816(acc[m][nf + 1], ah[m], b1f);
                }
            }
        }
        __syncthreads();
    }

    // ---------------- epilogue: accums -> SMEM -> gate math -> c,h ----------------
    float* zs = (float*)smg;   // 128 x ZS_STRIDE fp32 (133KB), reuses stage bufs
    #pragma unroll
    for (int m = 0; m < 2; m++) {
        int row = wm + m * 16 + (lane >> 2);
        #pragma unroll
        for (int n = 0; n < 8; n++) {
            int col = wn + n * 8 + (lane & 3) * 2;
            *(float2*)&zs[row * ZS_STRIDE + col]       = make_float2(acc[m][n][0], acc[m][n][1]);
            *(float2*)&zs[(row + 8) * ZS_STRIDE + col] = make_float2(acc[m][n][2], acc[m][n][3]);
        }
    }
    __syncthreads();

    #pragma unroll 1
    for (int it = 0; it < (MT * 64) / NTHR; it++) {    // 16 iterations
        int idx = tid + it * NTHR;
        int row = idx >> 6;
        int ul  = idx & 63;
        float4 z = *(const float4*)&zs[row * ZS_STRIDE + 4 * ul];
        float zi = z.x + s_bias[4 * ul + 0];
        float zf = z.y + s_bias[4 * ul + 1];
        float zg = z.z + s_bias[4 * ul + 2];
        float zo = z.w + s_bias[4 * ul + 3];

        const size_t gidx = (size_t)(b0 + row) * UU + u0 + ul;
        float cv = c[gidx];
        float cn = sigm(zf) * cv + sigm(zi) * tanhfast(zg);
        c[gidx] = cn;
        op[gidx] = __float2half_rn(sigm(zo) * tanhfast(cn));
    }
    #undef AT
    #undef BT
}

// ---------------- output kernel: only the indexed columns of pred ----------------
__global__ __launch_bounds__(256) void out_kernel(
    const f16* __restrict__ hp,
    const float* __restrict__ Wd, const float* __restrict__ bd,
    const int* __restrict__ oidx, int n_idx,
    float* __restrict__ out, int s, int S)
{
    const int wid  = threadIdx.x >> 5;
    const int lane = threadIdx.x & 31;
    const int b = blockIdx.x * 8 + wid;

    float a0 = 0.0f, a1 = 0.0f;                       // n_idx <= 2 fast path
    const int o0 = oidx[0];
    const int o1 = (n_idx > 1) ? oidx[1] : 0;
    #pragma unroll 4
    for (int i = 0; i < UU / 32; i++) {
        int u = lane + i * 32;
        float hv = __half2float(hp[(size_t)b * UU + u]);
        a0 += hv * Wd[(size_t)u * II + o0];
        a1 += hv * Wd[(size_t)u * II + o1];
    }
    #pragma unroll
    for (int off = 16; off > 0; off >>= 1) {
        a0 += __shfl_down_sync(0xFFFFFFFFu, a0, off);
        a1 += __shfl_down_sync(0xFFFFFFFFu, a1, off);
    }
    if (lane == 0) {
        out[((size_t)b * S + s) * n_idx + 0] = a0 + bd[o0];
        if (n_idx > 1) out[((size_t)b * S + s) * n_idx + 1] = a1 + bd[o1];
    }
}

// ---------------- host driver ----------------
extern "C" void kernel_launch(void* const* d_in, const int* in_sizes, int n_in,
                              void* d_out, int out_size)
{
    const float* inputs = (const float*)d_in[0];
    const float* Wk     = (const float*)d_in[1];
    const float* Wr     = (const float*)d_in[2];
    const float* bias   = (const float*)d_in[3];
    const float* Wd     = (const float*)d_in[4];
    const float* bd     = (const float*)d_in[5];
    const int*   oidx   = (const int*)d_in[6];
    float*       out    = (float*)d_out;

    const int n_idx = in_sizes[6];
    const int S     = out_size / (Bx * n_idx);

    f16 *xp, *hb, *wth, *wtl, *w2h, *w2l;
    float *cb, *b2;
    cudaGetSymbolAddress((void**)&xp, g_x);
    cudaGetSymbolAddress((void**)&hb, g_h);
    cudaGetSymbolAddress((void**)&cb, g_c);
    cudaGetSymbolAddress((void**)&wth, g_Wt_hi);
    cudaGetSymbolAddress((void**)&wtl, g_Wt_lo);
    cudaGetSymbolAddress((void**)&w2h, g_W2_hi);
    cudaGetSymbolAddress((void**)&w2l, g_W2_lo);
    cudaGetSymbolAddress((void**)&b2, g_b2);

    const int dyn_smem = 2 * 81920 + 1024;   // 164864 B
    cudaFuncSetAttribute(lstm_step_mma, cudaFuncAttributeMaxDynamicSharedMemorySize, dyn_smem);

    // one-time-per-launch prep
    prep_weights<<<NN, 256>>>(Wk, Wr);
    prep_w2<<<NN, 256>>>(Wk, Wr, Wd, bias, bd);
    prep_inputs<<<(Bx * TT * II) / 256, 256>>>(inputs);
    cudaMemsetAsync(hb, 0, sizeof(f16) * Bx * UU);   // zero buffer 0 only
    cudaMemsetAsync(cb, 0, sizeof(float) * Bx * UU);

    const dim3 grid(NN / NTL, Bx / MT);      // (16, 8) = 128 CTAs, single wave
    int cur = 0;

    // warmup: 256 steps, K = 1088 (x chunk + h)
    for (int t = 0; t < TT; t++) {
        lstm_step_mma<<<grid, NTHR, dyn_smem>>>(
            xp + (size_t)t * II, TT * II, 1,
            hb + (size_t)cur * Bx * UU,
            wth, wtl, KK,
            hb + (size_t)(cur ^ 1) * Bx * UU,
            cb, bias, KK / KC);
        cur ^= 1;
    }

    out_kernel<<<Bx / 8, 256>>>(hb + (size_t)cur * Bx * UU, Wd, bd, oidx, n_idx, out, 0, S);

    // decode: folded weights W' = Wr + Wd@Wk, K = 1024, no feedback kernel
    for (int s = 1; s < S; s++) {
        lstm_step_mma<<<grid, NTHR, dyn_smem>>>(
            (const f16*)0, 0, 0,
            hb + (size_t)cur * Bx * UU,
            w2h, w2l, UU,
            hb + (size_t)(cur ^ 1) * Bx * UU,
            cb, b2, UU / KC);
        cur ^= 1;
        out_kernel<<<Bx / 8, 256>>>(hb + (size_t)cur * Bx * UU, Wd, bd, oidx, n_idx, out, s, S);
    }
}